// round 14
// baseline (speedup 1.0000x reference)
#include <cuda_runtime.h>
#include <math.h>
#include <stdint.h>

// Problem constants (fixed shapes)
#define B_N 2048
#define D_N 512
#define H_N 512
#define A_N 18
#define T_N 16

#define BM 32              // rows per block
#define BNH 128            // cols per block (quarter of H)
#define NPART 4            // four column quarters
#define BKQ 16             // k per stage
#define STAGES 3
#define NKT (D_N / BKQ)    // 32 iterations
#define NBLK1 320          // >= worst-case work items

// ---------------- device scratch (no allocation allowed) ----------------
__device__ int   g_rowmap[B_N];
__device__ int   g_taskof[B_N];
__device__ float g_lpart[NPART][B_N][A_N];

// ---------------- mma / cp.async helpers ----------------
__device__ __forceinline__ void mma_tf32(float* c, const uint32_t* a, const uint32_t* b) {
    asm("mma.sync.aligned.m16n8k8.row.col.f32.tf32.tf32.f32 "
        "{%0,%1,%2,%3},{%4,%5,%6,%7},{%8,%9},{%0,%1,%2,%3};"
        : "+f"(c[0]), "+f"(c[1]), "+f"(c[2]), "+f"(c[3])
        : "r"(a[0]), "r"(a[1]), "r"(a[2]), "r"(a[3]), "r"(b[0]), "r"(b[1]));
}
__device__ __forceinline__ void cp16(uint32_t dst, const void* src) {
    asm volatile("cp.async.cg.shared.global [%0], [%1], 16;" :: "r"(dst), "l"(src));
}
__device__ __forceinline__ void cp_commit() {
    asm volatile("cp.async.commit_group;" ::: "memory");
}

// ---------------- shared memory (phase-aliased union) -----------------------
#define WS_STRIDE (BNH + 8)     // 136 floats
#define XS_STRIDE (BKQ + 4)     // 20 floats
#define W_STAGE_BYTES (BKQ * WS_STRIDE * 4)          // 8704
#define X_STAGE_BYTES (BM * XS_STRIDE * 4)           // 2560
union Smem {
    struct { int hist[64][T_N]; int rowmap[B_N]; } grp;
    struct { float Ws[STAGES][BKQ][WS_STRIDE]; float Xs[STAGES][BM][XS_STRIDE]; } p;
    struct { float W2T[A_N][BNH + 2]; float red[4][BM][A_N]; } e;
};

// ====== kernel 1: group + tf32 GEMM (cp.async, 3-stage) + fc2 partials =====
__global__ __launch_bounds__(256, 3)
void main_kernel(const float* __restrict__ xs,
                 const float* __restrict__ W1,
                 const float* __restrict__ b1,
                 const float* __restrict__ W2,
                 const int* __restrict__ task_id) {
    __shared__ Smem sm;
    __shared__ int soff[T_N + 1];
    __shared__ int s_totals[T_N];
    __shared__ int srow[BM];

    const int tid  = threadIdx.x;
    const int lane = tid & 31;
    const int warp = tid >> 5;             // 0..7
    const int b    = blockIdx.x;

    // ---------- Phase A: grouping (redundant per block, atomic-free) -------
    for (int i = tid; i < 64 * T_N; i += 256) ((int*)sm.grp.hist)[i] = 0;
    __syncthreads();

    int et[8], er[8];
#pragma unroll
    for (int it = 0; it < 8; it++) {
        const int chunk = it * 8 + warp;
        const int e = chunk * 32 + lane;
        const int t = task_id[e];
        unsigned m = __match_any_sync(0xffffffffu, t);
        int r = __popc(m & ((1u << lane) - 1u));
        et[it] = t; er[it] = r;
        if (r == 0) sm.grp.hist[chunk][t] = __popc(m);
    }
    __syncthreads();

#pragma unroll
    for (int s = 0; s < 2; s++) {
        const int t = warp * 2 + s;
        int v0 = sm.grp.hist[lane][t];
        int v1 = sm.grp.hist[lane + 32][t];
        int s0 = v0;
#pragma unroll
        for (int o = 1; o < 32; o <<= 1) {
            int u = __shfl_up_sync(0xffffffffu, s0, o);
            if (lane >= o) s0 += u;
        }
        int tot0 = __shfl_sync(0xffffffffu, s0, 31);
        int s1 = v1;
#pragma unroll
        for (int o = 1; o < 32; o <<= 1) {
            int u = __shfl_up_sync(0xffffffffu, s1, o);
            if (lane >= o) s1 += u;
        }
        s1 += tot0;
        int tot1 = __shfl_sync(0xffffffffu, s1, 31);
        sm.grp.hist[lane][t]      = s0 - v0;
        sm.grp.hist[lane + 32][t] = s1 - v1;
        if (lane == 0) s_totals[t] = tot1;
    }
    __syncthreads();

    if (warp == 0) {
        int v = (lane < T_N) ? s_totals[lane] : 0;
        int sv = v;
#pragma unroll
        for (int o = 1; o < 32; o <<= 1) {
            int u = __shfl_up_sync(0xffffffffu, sv, o);
            if (lane >= o) sv += u;
        }
        if (lane <= T_N) soff[lane] = sv - v;
    }
    __syncthreads();

#pragma unroll
    for (int it = 0; it < 8; it++) {
        const int chunk = it * 8 + warp;
        const int e = chunk * 32 + lane;
        const int t = et[it];
        const int p = soff[t] + sm.grp.hist[chunk][t] + er[it];
        sm.grp.rowmap[p] = e;
        if (b == it) { g_rowmap[p] = e; g_taskof[p] = t; }
    }
    __syncthreads();

    // ---------- work-item mapping: item = (task, 32-row slice, quarter) ----
    int t_my = -1, cb_my = 0, rowStart = 0, rowEnd = 0;
    {
        int acc = 0;
#pragma unroll
        for (int t = 0; t < T_N; t++) {
            const int cnt = soff[t + 1] - soff[t];
            const int n = ((cnt + BM - 1) / BM) * NPART;
            if (t_my < 0 && b < acc + n) {
                const int rem = b - acc;
                t_my = t; cb_my = rem & 3;
                rowStart = soff[t] + (rem >> 2) * BM;
                rowEnd   = soff[t + 1];
            }
            acc += n;
        }
    }
    if (t_my < 0) return;

    if (tid < BM) {
        const int p = rowStart + tid;
        srow[tid] = sm.grp.rowmap[(p < rowEnd) ? p : rowStart];
    }
    __syncthreads();   // sm.grp dead -> sm.p usable

    // ---------- Phase B: tf32 GEMM, 32 x 128, BKQ=16, 3-stage --------------
    const int cBase = cb_my * BNH;
    const int warp_m = warp >> 2;
    const int warp_n = warp & 3;
    const int g  = lane >> 2;
    const int tg = lane & 3;

    // loaders: W stage = 512 cp16 (2/thread); X stage = 128 cp16 (tid<128)
    const int wrow0 = tid >> 5;             // 0..7
    const int wc = (tid & 31) * 4;
    const int xr = (tid >> 2) & 31, xc = (tid & 3) * 4;

    // running global pointers (incremented; no per-iter IMAD chains)
    const float* wsrc0 = W1 + (size_t)t_my * D_N * H_N + cBase
                       + (size_t)wrow0 * H_N + wc;            // row wrow0
    const float* wsrc1 = wsrc0 + (size_t)8 * H_N;             // row wrow0+8
    const float* xsrc  = xs + (size_t)srow[xr] * D_N + xc;
    const size_t wstep = (size_t)BKQ * H_N;                   // per stage

    // smem dst bases (byte addresses); stage s = base + s*stage_bytes
    const uint32_t wdstA = (uint32_t)__cvta_generic_to_shared(&sm.p.Ws[0][wrow0][wc]);
    const uint32_t wdstB = (uint32_t)__cvta_generic_to_shared(&sm.p.Ws[0][wrow0 + 8][wc]);
    const uint32_t xdstA = (uint32_t)__cvta_generic_to_shared(&sm.p.Xs[0][xr][xc]);

    // prologue: stages 0,1
#pragma unroll
    for (int s = 0; s < STAGES - 1; s++) {
        cp16(wdstA + s * W_STAGE_BYTES, wsrc0);
        cp16(wdstB + s * W_STAGE_BYTES, wsrc1);
        if (tid < 128) cp16(xdstA + s * X_STAGE_BYTES, xsrc);
        wsrc0 += wstep; wsrc1 += wstep; xsrc += BKQ;
        cp_commit();
    }

    float acc[4][4];
#pragma unroll
    for (int j = 0; j < 4; j++)
#pragma unroll
        for (int r = 0; r < 4; r++) acc[j][r] = 0.f;

    int buf = 0;                 // stage index of current compute buffer
    int pbuf = STAGES - 1;       // stage index for next prefetch
    for (int kt = 0; kt < NKT; kt++) {
        if (kt < NKT - 1) asm volatile("cp.async.wait_group 1;" ::: "memory");
        else              asm volatile("cp.async.wait_group 0;" ::: "memory");
        __syncthreads();

        const int r0 = warp_m * 16 + g;
        const float* Xb = &sm.p.Xs[buf][0][0];
        const float* Wb = &sm.p.Ws[buf][0][0];
#pragma unroll
        for (int sk = 0; sk < 2; sk++) {
            const int k0 = sk * 8;
            uint32_t af[4];
            af[0] = __float_as_uint(Xb[r0 * XS_STRIDE + k0 + tg]);
            af[1] = __float_as_uint(Xb[(r0 + 8) * XS_STRIDE + k0 + tg]);
            af[2] = __float_as_uint(Xb[r0 * XS_STRIDE + k0 + tg + 4]);
            af[3] = __float_as_uint(Xb[(r0 + 8) * XS_STRIDE + k0 + tg + 4]);
#pragma unroll
            for (int wn = 0; wn < 4; wn++) {
                const int nc = warp_n * 32 + wn * 8 + g;
                uint32_t bf[2];
                bf[0] = __float_as_uint(Wb[(k0 + tg) * WS_STRIDE + nc]);
                bf[1] = __float_as_uint(Wb[(k0 + tg + 4) * WS_STRIDE + nc]);
                mma_tf32(acc[wn], af, bf);
            }
        }

        if (kt + 2 < NKT) {
            cp16(wdstA + pbuf * W_STAGE_BYTES, wsrc0);
            cp16(wdstB + pbuf * W_STAGE_BYTES, wsrc1);
            if (tid < 128) cp16(xdstA + pbuf * X_STAGE_BYTES, xsrc);
            wsrc0 += wstep; wsrc1 += wstep; xsrc += BKQ;
            cp_commit();
        }
        buf = (buf == STAGES - 1) ? 0 : buf + 1;
        pbuf = (pbuf == STAGES - 1) ? 0 : pbuf + 1;
    }
    __syncthreads();   // sm.p dead -> sm.e usable

    // ---------- stage W2^T (this quarter) ----------------------------------
    {
        const float* __restrict__ w2g = W2 + ((size_t)t_my * H_N + cBase) * A_N;
        for (int i = tid; i < BNH * A_N; i += 256) {
            const int c = i / A_N;
            const int a = i - c * A_N;
            sm.e.W2T[a][c] = w2g[i];
        }
    }
    __syncthreads();

    // ---------- fc2 partial: bias+relu from regs, 18-dot, quad reduce ------
    float part0[A_N], part1[A_N];
#pragma unroll
    for (int a = 0; a < A_N; a++) { part0[a] = 0.f; part1[a] = 0.f; }

    const float* __restrict__ b1g = b1 + (size_t)t_my * H_N + cBase + warp_n * 32;
#pragma unroll
    for (int wn = 0; wn < 4; wn++) {
        const int cl = wn * 8 + tg * 2;
        const float2 bv = *(const float2*)&b1g[cl];
        const float h00 = fmaxf(acc[wn][0] + bv.x, 0.f);
        const float h01 = fmaxf(acc[wn][1] + bv.y, 0.f);
        const float h10 = fmaxf(acc[wn][2] + bv.x, 0.f);
        const float h11 = fmaxf(acc[wn][3] + bv.y, 0.f);
        const int c = warp_n * 32 + cl;
#pragma unroll
        for (int a = 0; a < A_N; a++) {
            const float2 wv = *(const float2*)&sm.e.W2T[a][c];
            part0[a] = fmaf(h00, wv.x, fmaf(h01, wv.y, part0[a]));
            part1[a] = fmaf(h10, wv.x, fmaf(h11, wv.y, part1[a]));
        }
    }
#pragma unroll
    for (int a = 0; a < A_N; a++) {
#pragma unroll
        for (int o = 1; o <= 2; o <<= 1) {
            part0[a] += __shfl_xor_sync(0xffffffffu, part0[a], o);
            part1[a] += __shfl_xor_sync(0xffffffffu, part1[a], o);
        }
    }
    if (tg == 0) {
        const int r0 = warp_m * 16 + g;
#pragma unroll
        for (int a = 0; a < A_N; a++) {
            sm.e.red[warp_n][r0][a]     = part0[a];
            sm.e.red[warp_n][r0 + 8][a] = part1[a];
        }
    }
    __syncthreads();

    // ---------- write partial logits (sum over warp_n) ---------------------
    if (lane < A_N) {
#pragma unroll
        for (int i = 0; i < 4; i++) {
            const int row = warp * 4 + i;
            const int p = rowStart + row;
            if (p < rowEnd) {
                g_lpart[cb_my][p][lane] = sm.e.red[0][row][lane] + sm.e.red[1][row][lane]
                                        + sm.e.red[2][row][lane] + sm.e.red[3][row][lane];
            }
        }
    }
}

// =========== kernel 2: sum partials + bias + log_softmax + entropy =========
__global__ __launch_bounds__(256)
void head_kernel(const float* __restrict__ b2,
                 const int* __restrict__ action,
                 float* __restrict__ out) {
    const int tid = threadIdx.x;
    const int warp = tid >> 5;
    const int lane = tid & 31;
    const int p = blockIdx.x * 8 + warp;    // grid.x = B_N/8 = 256

    const int t = g_taskof[p];
    const int orig = g_rowmap[p];
    const bool act = lane < A_N;
    const int a = act ? lane : 0;

    float logit = b2[t * A_N + a];
#pragma unroll
    for (int cb = 0; cb < NPART; cb++) logit += g_lpart[cb][p][a];

    const float NEG_INF = __int_as_float(0xff800000);
    float lg = act ? logit : NEG_INF;
    float m = lg;
#pragma unroll
    for (int o = 16; o > 0; o >>= 1)
        m = fmaxf(m, __shfl_xor_sync(0xffffffffu, m, o));
    float e = act ? expf(logit - m) : 0.f;
    float v = act ? e * (logit - m) : 0.f;
    float S1 = e, S2 = v;
#pragma unroll
    for (int o = 16; o > 0; o >>= 1) {
        S1 += __shfl_xor_sync(0xffffffffu, S1, o);
        S2 += __shfl_xor_sync(0xffffffffu, S2, o);
    }
    float logS = logf(S1);
    float logp = logit - m - logS;
    float ent  = logS - S2 / S1;

    int a_star = action[orig];
    if (lane == a_star) out[B_N + orig] = logp;
    if (lane == 0) {
        out[orig]           = (float)a_star;
        out[2 * B_N + orig] = ent;
    }
}

// ---------------- launch ----------------
extern "C" void kernel_launch(void* const* d_in, const int* in_sizes, int n_in,
                              void* d_out, int out_size) {
    (void)in_sizes; (void)n_in; (void)out_size;
    const float* xs   = (const float*)d_in[0];
    const float* W1   = (const float*)d_in[1];
    const float* b1   = (const float*)d_in[2];
    const float* W2   = (const float*)d_in[3];
    const float* b2   = (const float*)d_in[4];
    const int*   task = (const int*)d_in[5];
    const int*   act  = (const int*)d_in[6];
    float* out = (float*)d_out;

    main_kernel<<<NBLK1, 256>>>(xs, W1, b1, W2, task);
    head_kernel<<<B_N / 8, 256>>>(b2, act, out);
}

// round 15
// speedup vs baseline: 1.2037x; 1.2037x over previous
#include <cuda_runtime.h>
#include <math.h>
#include <stdint.h>

// Problem constants (fixed shapes)
#define B_N 2048
#define D_N 512
#define H_N 512
#define A_N 18
#define T_N 16

#define BM 32              // rows per block
#define BNH 128            // cols per block (quarter of H)
#define NPART 4            // four column quarters
#define BKQ 16             // k per stage
#define STAGES 3
#define NKT (D_N / BKQ)    // 32 iterations
#define NBLK1 320          // >= max work items (<=320), ~2.2 blocks/SM

// ---------------- device scratch (no allocation allowed) ----------------
__device__ int   g_rowmap[B_N];
__device__ int   g_taskof[B_N];
__device__ float g_lpart[NPART][B_N][A_N];

// ---------------- mma / cp.async helpers ----------------
__device__ __forceinline__ void mma_tf32(float* c, const uint32_t* a, const uint32_t* b) {
    asm("mma.sync.aligned.m16n8k8.row.col.f32.tf32.tf32.f32 "
        "{%0,%1,%2,%3},{%4,%5,%6,%7},{%8,%9},{%0,%1,%2,%3};"
        : "+f"(c[0]), "+f"(c[1]), "+f"(c[2]), "+f"(c[3])
        : "r"(a[0]), "r"(a[1]), "r"(a[2]), "r"(a[3]), "r"(b[0]), "r"(b[1]));
}
__device__ __forceinline__ void cp16(uint32_t dst, const void* src) {
    asm volatile("cp.async.cg.shared.global [%0], [%1], 16;" :: "r"(dst), "l"(src));
}
__device__ __forceinline__ void cp_commit() {
    asm volatile("cp.async.commit_group;" ::: "memory");
}

// ---------------- shared memory (phase-aliased union) -----------------------
#define WS_STRIDE (BNH + 8)     // 136 floats: conflict-free B-frag LDS
#define XS_STRIDE (BKQ + 4)     // 20 floats: conflict-free A-frag LDS
union Smem {
    struct { int hist[64][T_N]; int rowmap[B_N]; } grp;                              // 12.3 KB
    struct { float Ws[STAGES][BKQ][WS_STRIDE]; float Xs[STAGES][BM][XS_STRIDE]; } p; // 33.6 KB
    struct { float W2T[A_N][BNH + 2]; float red[4][BM][A_N]; } e;                    // 18.3 KB
};

// ====== kernel 1: group + tf32 GEMM (cp.async, 1 barrier / 2 k-subtiles) ====
__global__ __launch_bounds__(256, 2)
void main_kernel(const float* __restrict__ xs,
                 const float* __restrict__ W1,
                 const float* __restrict__ b1,
                 const float* __restrict__ W2,
                 const int* __restrict__ task_id) {
    __shared__ Smem sm;
    __shared__ int soff[T_N + 1];
    __shared__ int s_totals[T_N];
    __shared__ int srow[BM];

    const int tid  = threadIdx.x;
    const int lane = tid & 31;
    const int warp = tid >> 5;             // 0..7
    const int b    = blockIdx.x;

    // ---------- Phase A: grouping (redundant per block, atomic-free) -------
    for (int i = tid; i < 64 * T_N; i += 256) ((int*)sm.grp.hist)[i] = 0;
    __syncthreads();

    int et[8], er[8];
#pragma unroll
    for (int it = 0; it < 8; it++) {
        const int chunk = it * 8 + warp;
        const int e = chunk * 32 + lane;
        const int t = task_id[e];
        unsigned m = __match_any_sync(0xffffffffu, t);
        int r = __popc(m & ((1u << lane) - 1u));
        et[it] = t; er[it] = r;
        if (r == 0) sm.grp.hist[chunk][t] = __popc(m);
    }
    __syncthreads();

#pragma unroll
    for (int s = 0; s < 2; s++) {
        const int t = warp * 2 + s;
        int v0 = sm.grp.hist[lane][t];
        int v1 = sm.grp.hist[lane + 32][t];
        int s0 = v0;
#pragma unroll
        for (int o = 1; o < 32; o <<= 1) {
            int u = __shfl_up_sync(0xffffffffu, s0, o);
            if (lane >= o) s0 += u;
        }
        int tot0 = __shfl_sync(0xffffffffu, s0, 31);
        int s1 = v1;
#pragma unroll
        for (int o = 1; o < 32; o <<= 1) {
            int u = __shfl_up_sync(0xffffffffu, s1, o);
            if (lane >= o) s1 += u;
        }
        s1 += tot0;
        int tot1 = __shfl_sync(0xffffffffu, s1, 31);
        sm.grp.hist[lane][t]      = s0 - v0;
        sm.grp.hist[lane + 32][t] = s1 - v1;
        if (lane == 0) s_totals[t] = tot1;
    }
    __syncthreads();

    if (warp == 0) {
        int v = (lane < T_N) ? s_totals[lane] : 0;
        int sv = v;
#pragma unroll
        for (int o = 1; o < 32; o <<= 1) {
            int u = __shfl_up_sync(0xffffffffu, sv, o);
            if (lane >= o) sv += u;
        }
        if (lane <= T_N) soff[lane] = sv - v;
    }
    __syncthreads();

#pragma unroll
    for (int it = 0; it < 8; it++) {
        const int chunk = it * 8 + warp;
        const int e = chunk * 32 + lane;
        const int t = et[it];
        const int p = soff[t] + sm.grp.hist[chunk][t] + er[it];
        sm.grp.rowmap[p] = e;
        if (b == it) { g_rowmap[p] = e; g_taskof[p] = t; }
    }
    __syncthreads();

    // ---------- work-item mapping: item = (task, 32-row slice, quarter) ----
    int t_my = -1, cb_my = 0, rowStart = 0, rowEnd = 0;
    {
        int acc = 0;
#pragma unroll
        for (int t = 0; t < T_N; t++) {
            const int cnt = soff[t + 1] - soff[t];
            const int n = ((cnt + BM - 1) / BM) * NPART;
            if (t_my < 0 && b < acc + n) {
                const int rem = b - acc;
                t_my = t; cb_my = rem & 3;
                rowStart = soff[t] + (rem >> 2) * BM;
                rowEnd   = soff[t + 1];
            }
            acc += n;
        }
    }
    if (t_my < 0) return;

    if (tid < BM) {
        const int p = rowStart + tid;
        srow[tid] = sm.grp.rowmap[(p < rowEnd) ? p : rowStart];
    }
    __syncthreads();   // sm.grp dead -> sm.p usable (and srow visible)

    // ---------- Phase B: tf32 GEMM, 32 x 128, BKQ=16, 3-stage --------------
    const int cBase = cb_my * BNH;
    const int warp_m = warp >> 2;           // 0..1 -> rows warp_m*16
    const int warp_n = warp & 3;            // 0..3 -> cols warp_n*32
    const int g  = lane >> 2;               // 0..7
    const int tg = lane & 3;                // 0..3

    // loaders: W stage = 16 rows x 128 floats = 512 cp16 (2/thread);
    //          X stage = 32 rows x 16 floats  = 128 cp16 (tid<128)
    const int wrow0 = tid >> 5;             // 0..7
    const int wrow1 = wrow0 + 8;            // 8..15
    const int wc = (tid & 31) * 4;
    const float* __restrict__ Wp = W1 + (size_t)t_my * D_N * H_N + cBase;
    const int xr = tid >> 2, xc = (tid & 3) * 4;   // tid<128: rows 0..31
    const float* __restrict__ xrp = xs + (size_t)srow[xr & 31] * D_N + xc;

    uint32_t wdst0[STAGES], wdst1[STAGES], xdst[STAGES];
#pragma unroll
    for (int s = 0; s < STAGES; s++) {
        wdst0[s] = (uint32_t)__cvta_generic_to_shared(&sm.p.Ws[s][wrow0][wc]);
        wdst1[s] = (uint32_t)__cvta_generic_to_shared(&sm.p.Ws[s][wrow1][wc]);
        xdst[s]  = (uint32_t)__cvta_generic_to_shared(&sm.p.Xs[s][xr & 31][xc]);
    }

    // prologue: issue stages 0,1
#pragma unroll
    for (int s = 0; s < STAGES - 1; s++) {
        cp16(wdst0[s], Wp + (size_t)(s * BKQ + wrow0) * H_N + wc);
        cp16(wdst1[s], Wp + (size_t)(s * BKQ + wrow1) * H_N + wc);
        if (tid < 128) cp16(xdst[s], xrp + s * BKQ);
        cp_commit();
    }

    float acc[4][4];
#pragma unroll
    for (int j = 0; j < 4; j++)
#pragma unroll
        for (int r = 0; r < 4; r++) acc[j][r] = 0.f;

    for (int kt = 0; kt < NKT; kt++) {
        if (kt < NKT - 1) asm volatile("cp.async.wait_group 1;" ::: "memory");
        else              asm volatile("cp.async.wait_group 0;" ::: "memory");
        __syncthreads();   // buf kt ready; all threads done reading buf kt-1

        const int buf = kt % 3;
        const int r0 = warp_m * 16 + g;
#pragma unroll
        for (int sk = 0; sk < 2; sk++) {
            const int k0 = sk * 8;
            uint32_t af[4];
            af[0] = __float_as_uint(sm.p.Xs[buf][r0][k0 + tg]);
            af[1] = __float_as_uint(sm.p.Xs[buf][r0 + 8][k0 + tg]);
            af[2] = __float_as_uint(sm.p.Xs[buf][r0][k0 + tg + 4]);
            af[3] = __float_as_uint(sm.p.Xs[buf][r0 + 8][k0 + tg + 4]);
#pragma unroll
            for (int wn = 0; wn < 4; wn++) {
                const int nc = warp_n * 32 + wn * 8 + g;
                uint32_t bf[2];
                bf[0] = __float_as_uint(sm.p.Ws[buf][k0 + tg][nc]);
                bf[1] = __float_as_uint(sm.p.Ws[buf][k0 + tg + 4][nc]);
                mma_tf32(acc[wn], af, bf);
            }
        }

        // issue stage kt+2 into buf (kt+2)%3 == (kt-1)%3 — safe post-barrier
        if (kt + 2 < NKT) {
            const int s = (kt + 2) % 3;
            cp16(wdst0[s], Wp + (size_t)((kt + 2) * BKQ + wrow0) * H_N + wc);
            cp16(wdst1[s], Wp + (size_t)((kt + 2) * BKQ + wrow1) * H_N + wc);
            if (tid < 128) cp16(xdst[s], xrp + (kt + 2) * BKQ);
            cp_commit();
        }
    }
    __syncthreads();   // sm.p dead -> sm.e usable

    // ---------- stage W2^T (this quarter) ----------------------------------
    {
        const float* __restrict__ w2g = W2 + ((size_t)t_my * H_N + cBase) * A_N;
        for (int i = tid; i < BNH * A_N; i += 256) {
            const int c = i / A_N;
            const int a = i - c * A_N;
            sm.e.W2T[a][c] = w2g[i];
        }
    }
    __syncthreads();

    // ---------- fc2 partial: bias+relu from regs, 18-dot, quad reduce ------
    float part0[A_N], part1[A_N];
#pragma unroll
    for (int a = 0; a < A_N; a++) { part0[a] = 0.f; part1[a] = 0.f; }

    const float* __restrict__ b1g = b1 + (size_t)t_my * H_N + cBase + warp_n * 32;
#pragma unroll
    for (int wn = 0; wn < 4; wn++) {
        const int cl = wn * 8 + tg * 2;
        const float2 bv = *(const float2*)&b1g[cl];
        const float h00 = fmaxf(acc[wn][0] + bv.x, 0.f);
        const float h01 = fmaxf(acc[wn][1] + bv.y, 0.f);
        const float h10 = fmaxf(acc[wn][2] + bv.x, 0.f);
        const float h11 = fmaxf(acc[wn][3] + bv.y, 0.f);
        const int c = warp_n * 32 + cl;
#pragma unroll
        for (int a = 0; a < A_N; a++) {
            const float2 wv = *(const float2*)&sm.e.W2T[a][c];
            part0[a] = fmaf(h00, wv.x, fmaf(h01, wv.y, part0[a]));
            part1[a] = fmaf(h10, wv.x, fmaf(h11, wv.y, part1[a]));
        }
    }
#pragma unroll
    for (int a = 0; a < A_N; a++) {
#pragma unroll
        for (int o = 1; o <= 2; o <<= 1) {
            part0[a] += __shfl_xor_sync(0xffffffffu, part0[a], o);
            part1[a] += __shfl_xor_sync(0xffffffffu, part1[a], o);
        }
    }
    if (tg == 0) {
        const int r0 = warp_m * 16 + g;
#pragma unroll
        for (int a = 0; a < A_N; a++) {
            sm.e.red[warp_n][r0][a]     = part0[a];
            sm.e.red[warp_n][r0 + 8][a] = part1[a];
        }
    }
    __syncthreads();

    // ---------- write partial logits (sum over warp_n) ---------------------
    if (lane < A_N) {
#pragma unroll
        for (int i = 0; i < 4; i++) {
            const int row = warp * 4 + i;
            const int p = rowStart + row;
            if (p < rowEnd) {
                g_lpart[cb_my][p][lane] = sm.e.red[0][row][lane] + sm.e.red[1][row][lane]
                                        + sm.e.red[2][row][lane] + sm.e.red[3][row][lane];
            }
        }
    }
}

// ====== kernel 2 (PDL secondary): partials + bias + log_softmax + entropy ===
__global__ __launch_bounds__(256)
void head_kernel(const float* __restrict__ b2,
                 const int* __restrict__ action,
                 float* __restrict__ out) {
#if __CUDA_ARCH__ >= 900
    cudaGridDependencySynchronize();   // wait for main_kernel's writes (PDL)
#endif
    const int tid = threadIdx.x;
    const int warp = tid >> 5;
    const int lane = tid & 31;
    const int p = blockIdx.x * 8 + warp;    // grid.x = B_N/8 = 256

    const int t = g_taskof[p];
    const int orig = g_rowmap[p];
    const bool act = lane < A_N;
    const int a = act ? lane : 0;

    float logit = b2[t * A_N + a];
#pragma unroll
    for (int cb = 0; cb < NPART; cb++) logit += g_lpart[cb][p][a];

    const float NEG_INF = __int_as_float(0xff800000);
    float lg = act ? logit : NEG_INF;
    float m = lg;
#pragma unroll
    for (int o = 16; o > 0; o >>= 1)
        m = fmaxf(m, __shfl_xor_sync(0xffffffffu, m, o));
    float e = act ? expf(logit - m) : 0.f;
    float v = act ? e * (logit - m) : 0.f;
    float S1 = e, S2 = v;
#pragma unroll
    for (int o = 16; o > 0; o >>= 1) {
        S1 += __shfl_xor_sync(0xffffffffu, S1, o);
        S2 += __shfl_xor_sync(0xffffffffu, S2, o);
    }
    float logS = logf(S1);
    float logp = logit - m - logS;
    float ent  = logS - S2 / S1;

    int a_star = action[orig];
    if (lane == a_star) out[B_N + orig] = logp;
    if (lane == 0) {
        out[orig]           = (float)a_star;
        out[2 * B_N + orig] = ent;
    }
}

// ---------------- launch ----------------
extern "C" void kernel_launch(void* const* d_in, const int* in_sizes, int n_in,
                              void* d_out, int out_size) {
    (void)in_sizes; (void)n_in; (void)out_size;
    const float* xs   = (const float*)d_in[0];
    const float* W1   = (const float*)d_in[1];
    const float* b1   = (const float*)d_in[2];
    const float* W2   = (const float*)d_in[3];
    const float* b2   = (const float*)d_in[4];
    const int*   task = (const int*)d_in[5];
    const int*   act  = (const int*)d_in[6];
    float* out = (float*)d_out;

    main_kernel<<<NBLK1, 256>>>(xs, W1, b1, W2, task);

    // head as PDL secondary: its launch/prologue overlaps main_kernel's tail;
    // cudaGridDependencySynchronize() inside guards the g_lpart reads.
    cudaLaunchConfig_t cfg = {};
    cfg.gridDim  = dim3(B_N / 8, 1, 1);
    cfg.blockDim = dim3(256, 1, 1);
    cfg.stream   = 0;
    cudaLaunchAttribute attrs[1];
    attrs[0].id = cudaLaunchAttributeProgrammaticStreamSerialization;
    attrs[0].val.programmaticStreamSerializationAllowed = 1;
    cfg.attrs = attrs;
    cfg.numAttrs = 1;
    cudaError_t err = cudaLaunchKernelEx(&cfg, head_kernel, b2, act, out);
    if (err != cudaSuccess) {
        // fallback: plain launch (still correct, just serialized)
        head_kernel<<<B_N / 8, 256>>>(b2, act, out);
    }
}

// round 16
// speedup vs baseline: 1.2063x; 1.0021x over previous
#include <cuda_runtime.h>
#include <math.h>
#include <stdint.h>

// Problem constants (fixed shapes)
#define B_N 2048
#define D_N 512
#define H_N 512
#define A_N 18
#define T_N 16

#define BM 32              // rows per block
#define BNH 128            // cols per block (quarter of H)
#define NPART 4            // four column quarters
#define BKQ 16             // k per stage
#define STAGES 4           // 2 stages of lookahead in flight
#define NKT (D_N / BKQ)    // 32 iterations
#define NBLK1 320          // >= max work items (<=320), ~2.2 blocks/SM

// ---------------- device scratch (no allocation allowed) ----------------
__device__ int   g_rowmap[B_N];
__device__ int   g_taskof[B_N];
__device__ float g_lpart[NPART][B_N][A_N];

// ---------------- mma / cp.async helpers ----------------
__device__ __forceinline__ void mma_tf32(float* c, const uint32_t* a, const uint32_t* b) {
    asm("mma.sync.aligned.m16n8k8.row.col.f32.tf32.tf32.f32 "
        "{%0,%1,%2,%3},{%4,%5,%6,%7},{%8,%9},{%0,%1,%2,%3};"
        : "+f"(c[0]), "+f"(c[1]), "+f"(c[2]), "+f"(c[3])
        : "r"(a[0]), "r"(a[1]), "r"(a[2]), "r"(a[3]), "r"(b[0]), "r"(b[1]));
}
__device__ __forceinline__ void cp16(uint32_t dst, const void* src) {
    asm volatile("cp.async.cg.shared.global [%0], [%1], 16;" :: "r"(dst), "l"(src));
}
__device__ __forceinline__ void cp_commit() {
    asm volatile("cp.async.commit_group;" ::: "memory");
}

// ---------------- shared memory (phase-aliased union) -----------------------
#define WS_STRIDE (BNH + 8)     // 136 floats: conflict-free B-frag LDS
#define XS_STRIDE (BKQ + 4)     // 20 floats: conflict-free A-frag LDS
union Smem {
    struct { int hist[64][T_N]; int rowmap[B_N]; } grp;                              // 12.3 KB
    struct { float Ws[STAGES][BKQ][WS_STRIDE]; float Xs[STAGES][BM][XS_STRIDE]; } p; // 44.0 KB
    struct { float W2T[A_N][BNH + 2]; float red[4][BM][A_N]; } e;                    // 18.3 KB
};

// ====== kernel 1: group + tf32 GEMM (cp.async 4-stage) + fc2 partials ======
__global__ __launch_bounds__(256, 2)
void main_kernel(const float* __restrict__ xs,
                 const float* __restrict__ W1,
                 const float* __restrict__ b1,
                 const float* __restrict__ W2,
                 const int* __restrict__ task_id) {
    __shared__ Smem sm;
    __shared__ int soff[T_N + 1];
    __shared__ int s_totals[T_N];
    __shared__ int srow[BM];

    const int tid  = threadIdx.x;
    const int lane = tid & 31;
    const int warp = tid >> 5;             // 0..7
    const int b    = blockIdx.x;

    // ---------- Phase A: grouping (redundant per block, atomic-free) -------
    for (int i = tid; i < 64 * T_N; i += 256) ((int*)sm.grp.hist)[i] = 0;
    __syncthreads();

    int et[8], er[8];
#pragma unroll
    for (int it = 0; it < 8; it++) {
        const int chunk = it * 8 + warp;
        const int e = chunk * 32 + lane;
        const int t = task_id[e];
        unsigned m = __match_any_sync(0xffffffffu, t);
        int r = __popc(m & ((1u << lane) - 1u));
        et[it] = t; er[it] = r;
        if (r == 0) sm.grp.hist[chunk][t] = __popc(m);
    }
    __syncthreads();

#pragma unroll
    for (int s = 0; s < 2; s++) {
        const int t = warp * 2 + s;
        int v0 = sm.grp.hist[lane][t];
        int v1 = sm.grp.hist[lane + 32][t];
        int s0 = v0;
#pragma unroll
        for (int o = 1; o < 32; o <<= 1) {
            int u = __shfl_up_sync(0xffffffffu, s0, o);
            if (lane >= o) s0 += u;
        }
        int tot0 = __shfl_sync(0xffffffffu, s0, 31);
        int s1 = v1;
#pragma unroll
        for (int o = 1; o < 32; o <<= 1) {
            int u = __shfl_up_sync(0xffffffffu, s1, o);
            if (lane >= o) s1 += u;
        }
        s1 += tot0;
        int tot1 = __shfl_sync(0xffffffffu, s1, 31);
        sm.grp.hist[lane][t]      = s0 - v0;
        sm.grp.hist[lane + 32][t] = s1 - v1;
        if (lane == 0) s_totals[t] = tot1;
    }
    __syncthreads();

    if (warp == 0) {
        int v = (lane < T_N) ? s_totals[lane] : 0;
        int sv = v;
#pragma unroll
        for (int o = 1; o < 32; o <<= 1) {
            int u = __shfl_up_sync(0xffffffffu, sv, o);
            if (lane >= o) sv += u;
        }
        if (lane <= T_N) soff[lane] = sv - v;
    }
    __syncthreads();

#pragma unroll
    for (int it = 0; it < 8; it++) {
        const int chunk = it * 8 + warp;
        const int e = chunk * 32 + lane;
        const int t = et[it];
        const int p = soff[t] + sm.grp.hist[chunk][t] + er[it];
        sm.grp.rowmap[p] = e;
        if (b == it) { g_rowmap[p] = e; g_taskof[p] = t; }
    }
    __syncthreads();

    // ---------- work-item mapping: item = (task, 32-row slice, quarter) ----
    int t_my = -1, cb_my = 0, rowStart = 0, rowEnd = 0;
    {
        int acc = 0;
#pragma unroll
        for (int t = 0; t < T_N; t++) {
            const int cnt = soff[t + 1] - soff[t];
            const int n = ((cnt + BM - 1) / BM) * NPART;
            if (t_my < 0 && b < acc + n) {
                const int rem = b - acc;
                t_my = t; cb_my = rem & 3;
                rowStart = soff[t] + (rem >> 2) * BM;
                rowEnd   = soff[t + 1];
            }
            acc += n;
        }
    }
    if (t_my < 0) return;

    if (tid < BM) {
        const int p = rowStart + tid;
        srow[tid] = sm.grp.rowmap[(p < rowEnd) ? p : rowStart];
    }
    __syncthreads();   // sm.grp dead -> sm.p usable (and srow visible)

    // ---------- Phase B: tf32 GEMM, 32 x 128, BKQ=16, 4-stage --------------
    const int cBase = cb_my * BNH;
    const int warp_m = warp >> 2;           // 0..1 -> rows warp_m*16
    const int warp_n = warp & 3;            // 0..3 -> cols warp_n*32
    const int g  = lane >> 2;               // 0..7
    const int tg = lane & 3;                // 0..3

    // loaders: W stage = 16 rows x 128 floats = 512 cp16 (2/thread);
    //          X stage = 32 rows x 16 floats  = 128 cp16 (tid<128)
    const int wrow0 = tid >> 5;             // 0..7
    const int wrow1 = wrow0 + 8;            // 8..15
    const int wc = (tid & 31) * 4;
    const float* __restrict__ Wp = W1 + (size_t)t_my * D_N * H_N + cBase;
    const int xr = tid >> 2, xc = (tid & 3) * 4;   // tid<128: rows 0..31
    const float* __restrict__ xrp = xs + (size_t)srow[xr & 31] * D_N + xc;

    uint32_t wdst0[STAGES], wdst1[STAGES], xdst[STAGES];
#pragma unroll
    for (int s = 0; s < STAGES; s++) {
        wdst0[s] = (uint32_t)__cvta_generic_to_shared(&sm.p.Ws[s][wrow0][wc]);
        wdst1[s] = (uint32_t)__cvta_generic_to_shared(&sm.p.Ws[s][wrow1][wc]);
        xdst[s]  = (uint32_t)__cvta_generic_to_shared(&sm.p.Xs[s][xr & 31][xc]);
    }

    // prologue: issue stages 0..2
#pragma unroll
    for (int s = 0; s < STAGES - 1; s++) {
        cp16(wdst0[s], Wp + (size_t)(s * BKQ + wrow0) * H_N + wc);
        cp16(wdst1[s], Wp + (size_t)(s * BKQ + wrow1) * H_N + wc);
        if (tid < 128) cp16(xdst[s], xrp + s * BKQ);
        cp_commit();
    }

    float acc[4][4];
#pragma unroll
    for (int j = 0; j < 4; j++)
#pragma unroll
        for (int r = 0; r < 4; r++) acc[j][r] = 0.f;

    for (int kt = 0; kt < NKT; kt++) {
        if (kt < NKT - 2)       asm volatile("cp.async.wait_group 2;" ::: "memory");
        else if (kt == NKT - 2) asm volatile("cp.async.wait_group 1;" ::: "memory");
        else                    asm volatile("cp.async.wait_group 0;" ::: "memory");
        __syncthreads();   // buf kt ready; all threads done reading buf kt-1

        const int buf = kt & 3;
        const int r0 = warp_m * 16 + g;
#pragma unroll
        for (int sk = 0; sk < 2; sk++) {
            const int k0 = sk * 8;
            uint32_t af[4];
            af[0] = __float_as_uint(sm.p.Xs[buf][r0][k0 + tg]);
            af[1] = __float_as_uint(sm.p.Xs[buf][r0 + 8][k0 + tg]);
            af[2] = __float_as_uint(sm.p.Xs[buf][r0][k0 + tg + 4]);
            af[3] = __float_as_uint(sm.p.Xs[buf][r0 + 8][k0 + tg + 4]);
#pragma unroll
            for (int wn = 0; wn < 4; wn++) {
                const int nc = warp_n * 32 + wn * 8 + g;
                uint32_t bf[2];
                bf[0] = __float_as_uint(sm.p.Ws[buf][k0 + tg][nc]);
                bf[1] = __float_as_uint(sm.p.Ws[buf][k0 + tg + 4][nc]);
                mma_tf32(acc[wn], af, bf);
            }
        }

        // issue stage kt+3 into buf (kt+3)&3 == (kt-1)&3 — safe post-barrier
        if (kt + 3 < NKT) {
            const int s = (kt + 3) & 3;
            cp16(wdst0[s], Wp + (size_t)((kt + 3) * BKQ + wrow0) * H_N + wc);
            cp16(wdst1[s], Wp + (size_t)((kt + 3) * BKQ + wrow1) * H_N + wc);
            if (tid < 128) cp16(xdst[s], xrp + (kt + 3) * BKQ);
            cp_commit();
        }
    }
    __syncthreads();   // sm.p dead -> sm.e usable

    // ---------- stage W2^T (this quarter) ----------------------------------
    {
        const float* __restrict__ w2g = W2 + ((size_t)t_my * H_N + cBase) * A_N;
        for (int i = tid; i < BNH * A_N; i += 256) {
            const int c = i / A_N;
            const int a = i - c * A_N;
            sm.e.W2T[a][c] = w2g[i];
        }
    }
    __syncthreads();

    // ---------- fc2 partial: bias+relu from regs, 18-dot, quad reduce ------
    float part0[A_N], part1[A_N];
#pragma unroll
    for (int a = 0; a < A_N; a++) { part0[a] = 0.f; part1[a] = 0.f; }

    const float* __restrict__ b1g = b1 + (size_t)t_my * H_N + cBase + warp_n * 32;
#pragma unroll
    for (int wn = 0; wn < 4; wn++) {
        const int cl = wn * 8 + tg * 2;
        const float2 bv = *(const float2*)&b1g[cl];
        const float h00 = fmaxf(acc[wn][0] + bv.x, 0.f);
        const float h01 = fmaxf(acc[wn][1] + bv.y, 0.f);
        const float h10 = fmaxf(acc[wn][2] + bv.x, 0.f);
        const float h11 = fmaxf(acc[wn][3] + bv.y, 0.f);
        const int c = warp_n * 32 + cl;
#pragma unroll
        for (int a = 0; a < A_N; a++) {
            const float2 wv = *(const float2*)&sm.e.W2T[a][c];
            part0[a] = fmaf(h00, wv.x, fmaf(h01, wv.y, part0[a]));
            part1[a] = fmaf(h10, wv.x, fmaf(h11, wv.y, part1[a]));
        }
    }
#pragma unroll
    for (int a = 0; a < A_N; a++) {
#pragma unroll
        for (int o = 1; o <= 2; o <<= 1) {
            part0[a] += __shfl_xor_sync(0xffffffffu, part0[a], o);
            part1[a] += __shfl_xor_sync(0xffffffffu, part1[a], o);
        }
    }
    if (tg == 0) {
        const int r0 = warp_m * 16 + g;
#pragma unroll
        for (int a = 0; a < A_N; a++) {
            sm.e.red[warp_n][r0][a]     = part0[a];
            sm.e.red[warp_n][r0 + 8][a] = part1[a];
        }
    }
    __syncthreads();

    // ---------- write partial logits (sum over warp_n) ---------------------
    if (lane < A_N) {
#pragma unroll
        for (int i = 0; i < 4; i++) {
            const int row = warp * 4 + i;
            const int p = rowStart + row;
            if (p < rowEnd) {
                g_lpart[cb_my][p][lane] = sm.e.red[0][row][lane] + sm.e.red[1][row][lane]
                                        + sm.e.red[2][row][lane] + sm.e.red[3][row][lane];
            }
        }
    }
}

// ====== kernel 2 (PDL secondary): partials + bias + log_softmax + entropy ===
__global__ __launch_bounds__(256)
void head_kernel(const float* __restrict__ b2,
                 const int* __restrict__ action,
                 float* __restrict__ out) {
#if __CUDA_ARCH__ >= 900
    cudaGridDependencySynchronize();   // wait for main_kernel's writes (PDL)
#endif
    const int tid = threadIdx.x;
    const int warp = tid >> 5;
    const int lane = tid & 31;
    const int p = blockIdx.x * 8 + warp;    // grid.x = B_N/8 = 256

    const int t = g_taskof[p];
    const int orig = g_rowmap[p];
    const bool act = lane < A_N;
    const int a = act ? lane : 0;

    float logit = b2[t * A_N + a];
#pragma unroll
    for (int cb = 0; cb < NPART; cb++) logit += g_lpart[cb][p][a];

    const float NEG_INF = __int_as_float(0xff800000);
    float lg = act ? logit : NEG_INF;
    float m = lg;
#pragma unroll
    for (int o = 16; o > 0; o >>= 1)
        m = fmaxf(m, __shfl_xor_sync(0xffffffffu, m, o));
    float e = act ? expf(logit - m) : 0.f;
    float v = act ? e * (logit - m) : 0.f;
    float S1 = e, S2 = v;
#pragma unroll
    for (int o = 16; o > 0; o >>= 1) {
        S1 += __shfl_xor_sync(0xffffffffu, S1, o);
        S2 += __shfl_xor_sync(0xffffffffu, S2, o);
    }
    float logS = logf(S1);
    float logp = logit - m - logS;
    float ent  = logS - S2 / S1;

    int a_star = action[orig];
    if (lane == a_star) out[B_N + orig] = logp;
    if (lane == 0) {
        out[orig]           = (float)a_star;
        out[2 * B_N + orig] = ent;
    }
}

// ---------------- launch ----------------
extern "C" void kernel_launch(void* const* d_in, const int* in_sizes, int n_in,
                              void* d_out, int out_size) {
    (void)in_sizes; (void)n_in; (void)out_size;
    const float* xs   = (const float*)d_in[0];
    const float* W1   = (const float*)d_in[1];
    const float* b1   = (const float*)d_in[2];
    const float* W2   = (const float*)d_in[3];
    const float* b2   = (const float*)d_in[4];
    const int*   task = (const int*)d_in[5];
    const int*   act  = (const int*)d_in[6];
    float* out = (float*)d_out;

    main_kernel<<<NBLK1, 256>>>(xs, W1, b1, W2, task);

    // head as PDL secondary: launch/prologue overlaps main_kernel's tail
    cudaLaunchConfig_t cfg = {};
    cfg.gridDim  = dim3(B_N / 8, 1, 1);
    cfg.blockDim = dim3(256, 1, 1);
    cfg.stream   = 0;
    cudaLaunchAttribute attrs[1];
    attrs[0].id = cudaLaunchAttributeProgrammaticStreamSerialization;
    attrs[0].val.programmaticStreamSerializationAllowed = 1;
    cfg.attrs = attrs;
    cfg.numAttrs = 1;
    cudaError_t err = cudaLaunchKernelEx(&cfg, head_kernel, b2, act, out);
    if (err != cudaSuccess) {
        head_kernel<<<B_N / 8, 256>>>(b2, act, out);
    }
}